// round 3
// baseline (speedup 1.0000x reference)
#include <cuda_runtime.h>
#include <cstdint>

#define N_NODES 100000
#define N_EDGES 1000000
#define D 64

// Scratch (device globals — no allocations allowed)
__device__ float g_agg[N_NODES * D];
__device__ float g_deg[N_NODES];

// ---------------------------------------------------------------------------
// Kernel 1: zero the scratch accumulators
// ---------------------------------------------------------------------------
__global__ __launch_bounds__(256) void zero_kernel() {
    const int stride = gridDim.x * blockDim.x;
    int i = blockIdx.x * blockDim.x + threadIdx.x;
    float4 z = make_float4(0.f, 0.f, 0.f, 0.f);
    float4* agg4 = reinterpret_cast<float4*>(g_agg);
    const int total4 = (N_NODES * D) / 4;
    for (int idx = i; idx < total4; idx += stride) agg4[idx] = z;
    for (int idx = i; idx < N_NODES; idx += stride) g_deg[idx] = 0.f;
}

// ---------------------------------------------------------------------------
// Kernel 2: edge scatter. 16 lanes per edge; each lane moves one float4.
// edge_index is INT32 (JAX x64 disabled downcasts the reference's int64).
// Vector RED (red.global.add.v4.f32) — 1/4 the atomic instruction count.
// ---------------------------------------------------------------------------
__global__ __launch_bounds__(256) void scatter_kernel(
    const float* __restrict__ x, const int* __restrict__ ei)
{
    const int warp = blockIdx.x * 8 + (threadIdx.x >> 5);
    const int lane = threadIdx.x & 31;
    const int sub  = lane >> 4;    // which of the 2 edges this warp handles
    const int j    = lane & 15;    // float4 slot within the 64-dim row

    const int e = warp * 2 + sub;  // grid sized exactly: no guard
    int src = 0, dst = 0;
    if (j == 0) {
        src = __ldg(ei + e);
        dst = __ldg(ei + N_EDGES + e);
    }
    src = __shfl_sync(0xffffffffu, src, 0, 16);
    dst = __shfl_sync(0xffffffffu, dst, 0, 16);

    const float4 v = __ldg(reinterpret_cast<const float4*>(x) + (size_t)src * 16 + j);
    float* p = g_agg + (size_t)dst * D + j * 4;
    asm volatile("red.global.add.v4.f32 [%0], {%1,%2,%3,%4};"
                 :: "l"(p), "f"(v.x), "f"(v.y), "f"(v.z), "f"(v.w) : "memory");
    if (j == 0) atomicAdd(g_deg + dst, 1.0f);
}

// ---------------------------------------------------------------------------
// Kernel 3: out = relu(mean @ Wl^T + b + x @ Wr^T)
// Block: 128 nodes x 64 outputs. 256 threads, each owns 8 nodes x 4 outputs.
// Accumulation in packed f32x2 (fma.rn.f32x2): 2 nodes per 64-bit register.
// ---------------------------------------------------------------------------
#define WPAD 68      // 64 + 4 floats (keeps 16B alignment)
#define APAD 132     // 128 + 4 floats (keeps 16B alignment)

__global__ __launch_bounds__(256) void out_kernel(
    const float* __restrict__ x,
    const float* __restrict__ Wl,
    const float* __restrict__ bl,
    const float* __restrict__ Wr,
    float* __restrict__ out)
{
    extern __shared__ float sm[];
    float* sWl = sm;                        // [64][WPAD]  (k-major, transposed)
    float* sWr = sWl + D * WPAD;            // [64][WPAD]
    float* sA  = sWr + D * WPAD;            // [64][APAD]  mean, k-major
    float* sX  = sA  + D * APAD;            // [64][APAD]  x, k-major
    float* sB  = sX  + D * APAD;            // [64]
    float* sR  = sB  + D;                   // [128] reciprocal degree

    const int tid = threadIdx.x;
    const int tx  = tid & 15;               // output group: o = tx*4 .. tx*4+3
    const int ty  = tid >> 4;               // node group:   n = ty*8 .. ty*8+7
    const int node0 = blockIdx.x * 128;

    // --- load W (transpose [o][k] -> [k][o]) ---
    for (int t = tid; t < 1024; t += 256) {
        const int o = t >> 4, k = (t & 15) * 4;
        float4 w = __ldg(reinterpret_cast<const float4*>(Wl) + t);
        sWl[(k+0)*WPAD+o]=w.x; sWl[(k+1)*WPAD+o]=w.y;
        sWl[(k+2)*WPAD+o]=w.z; sWl[(k+3)*WPAD+o]=w.w;
        float4 u = __ldg(reinterpret_cast<const float4*>(Wr) + t);
        sWr[(k+0)*WPAD+o]=u.x; sWr[(k+1)*WPAD+o]=u.y;
        sWr[(k+2)*WPAD+o]=u.z; sWr[(k+3)*WPAD+o]=u.w;
    }
    if (tid < D) sB[tid] = __ldg(bl + tid);
    if (tid < 128) {
        const int n = node0 + tid;
        const float dg = (n < N_NODES) ? g_deg[n] : 1.f;
        sR[tid] = 1.f / fmaxf(dg, 1.f);
    }
    __syncthreads();

    // --- load + transpose the 128x64 mean / x tiles ---
    for (int t = tid; t < 2048; t += 256) {
        const int node = t >> 4, kq = t & 15, k = kq * 4;
        const int gn = node0 + node;
        float4 a  = make_float4(0.f,0.f,0.f,0.f);
        float4 xv = a;
        if (gn < N_NODES) {
            a  = __ldg(reinterpret_cast<const float4*>(g_agg) + (size_t)gn*16 + kq);
            xv = __ldg(reinterpret_cast<const float4*>(x)     + (size_t)gn*16 + kq);
        }
        const float r = sR[node];
        sA[(k+0)*APAD+node]=a.x*r; sA[(k+1)*APAD+node]=a.y*r;
        sA[(k+2)*APAD+node]=a.z*r; sA[(k+3)*APAD+node]=a.w*r;
        sX[(k+0)*APAD+node]=xv.x;  sX[(k+1)*APAD+node]=xv.y;
        sX[(k+2)*APAD+node]=xv.z;  sX[(k+3)*APAD+node]=xv.w;
    }
    __syncthreads();

    // --- register-tile GEMM with packed f32x2 FMA ---
    const int nb = ty * 8;
    const int ob = tx * 4;

    unsigned long long acc[4][4];   // [node-pair][output], bias preloaded
    #pragma unroll
    for (int o = 0; o < 4; o++) {
        const float b = sB[ob + o];
        unsigned long long bp;
        asm("mov.b64 %0, {%1, %2};" : "=l"(bp) : "f"(b), "f"(b));
        #pragma unroll
        for (int m = 0; m < 4; m++) acc[m][o] = bp;
    }

    #pragma unroll 8
    for (int k = 0; k < D; k++) {
        const float4 wl4 = *reinterpret_cast<const float4*>(sWl + k*WPAD + ob);
        const float4 wr4 = *reinterpret_cast<const float4*>(sWr + k*WPAD + ob);
        const ulonglong2 aA = *reinterpret_cast<const ulonglong2*>(sA + k*APAD + nb);
        const ulonglong2 aB = *reinterpret_cast<const ulonglong2*>(sA + k*APAD + nb + 4);
        const ulonglong2 xA = *reinterpret_cast<const ulonglong2*>(sX + k*APAD + nb);
        const ulonglong2 xB = *reinterpret_cast<const ulonglong2*>(sX + k*APAD + nb + 4);
        const unsigned long long ap[4] = {aA.x, aA.y, aB.x, aB.y};
        const unsigned long long xp[4] = {xA.x, xA.y, xB.x, xB.y};
        const float wlv[4] = {wl4.x, wl4.y, wl4.z, wl4.w};
        const float wrv[4] = {wr4.x, wr4.y, wr4.z, wr4.w};
        #pragma unroll
        for (int o = 0; o < 4; o++) {
            unsigned long long wl2, wr2;
            asm("mov.b64 %0, {%1, %2};" : "=l"(wl2) : "f"(wlv[o]), "f"(wlv[o]));
            asm("mov.b64 %0, {%1, %2};" : "=l"(wr2) : "f"(wrv[o]), "f"(wrv[o]));
            #pragma unroll
            for (int m = 0; m < 4; m++) {
                asm("fma.rn.f32x2 %0, %1, %2, %0;" : "+l"(acc[m][o]) : "l"(ap[m]), "l"(wl2));
                asm("fma.rn.f32x2 %0, %1, %2, %0;" : "+l"(acc[m][o]) : "l"(xp[m]), "l"(wr2));
            }
        }
    }

    // --- epilogue: ReLU + store ---
    #pragma unroll
    for (int m = 0; m < 4; m++) {
        float lo[4], hi[4];
        #pragma unroll
        for (int o = 0; o < 4; o++)
            asm("mov.b64 {%0, %1}, %2;" : "=f"(lo[o]), "=f"(hi[o]) : "l"(acc[m][o]));
        const int g0 = node0 + nb + m * 2;
        if (g0 < N_NODES) {
            float4 v = make_float4(fmaxf(lo[0],0.f), fmaxf(lo[1],0.f),
                                   fmaxf(lo[2],0.f), fmaxf(lo[3],0.f));
            *reinterpret_cast<float4*>(out + (size_t)g0*D + ob) = v;
        }
        if (g0 + 1 < N_NODES) {
            float4 v = make_float4(fmaxf(hi[0],0.f), fmaxf(hi[1],0.f),
                                   fmaxf(hi[2],0.f), fmaxf(hi[3],0.f));
            *reinterpret_cast<float4*>(out + (size_t)(g0+1)*D + ob) = v;
        }
    }
}

// ---------------------------------------------------------------------------
extern "C" void kernel_launch(void* const* d_in, const int* in_sizes, int n_in,
                              void* d_out, int out_size)
{
    const float* x  = (const float*)d_in[0];
    const int*   ei = (const int*)d_in[1];     // int32! (JAX x64 disabled)
    const float* Wl = (const float*)d_in[2];
    const float* bl = (const float*)d_in[3];
    const float* Wr = (const float*)d_in[4];
    float* out = (float*)d_out;

    const int smem_bytes = (2 * D * WPAD + 2 * D * APAD + D + 128) * sizeof(float);
    cudaFuncSetAttribute(out_kernel, cudaFuncAttributeMaxDynamicSharedMemorySize, smem_bytes);

    zero_kernel<<<2048, 256>>>();
    scatter_kernel<<<N_EDGES / 16, 256>>>(x, ei);   // 2 edges/warp * 8 warps = 16 edges/block
    out_kernel<<<(N_NODES + 127) / 128, 256, smem_bytes>>>(x, Wl, bl, Wr, out);
}

// round 5
// speedup vs baseline: 1.8950x; 1.8950x over previous
#include <cuda_runtime.h>
#include <cstdint>

#define N_NODES 100000
#define N_EDGES 1000000
#define D 64
#define CAP 64           // padded CSR slots per node (Poisson(10): overflow ~impossible, fallback exists)
#define MAX_OVF 32768

// Scratch (device globals — no allocations allowed)
__device__ __align__(16) float g_mean[N_NODES * D];
__device__ int  g_cnt[N_NODES];
__device__ __align__(16) int g_csr[N_NODES * CAP];
__device__ int  g_ovf_n;
__device__ int  g_ovf[MAX_OVF];

// ---------------------------------------------------------------------------
// Kernel 1: zero degree counters + overflow counter (g_mean fully overwritten)
// ---------------------------------------------------------------------------
__global__ __launch_bounds__(256) void zero_kernel() {
    const int stride = gridDim.x * blockDim.x;
    int i = blockIdx.x * blockDim.x + threadIdx.x;
    for (int idx = i; idx < N_NODES; idx += stride) g_cnt[idx] = 0;
    if (i == 0) g_ovf_n = 0;
}

// ---------------------------------------------------------------------------
// Kernel 2: CSR fill. pos = atomicAdd(cnt[dst]); csr[dst*CAP+pos] = src.
// ---------------------------------------------------------------------------
__global__ __launch_bounds__(256) void fill_kernel(const int* __restrict__ ei) {
    const int e = blockIdx.x * 256 + threadIdx.x;
    if (e >= N_EDGES) return;
    const int dst = __ldg(ei + N_EDGES + e);
    const int src = __ldg(ei + e);
    const int pos = atomicAdd(g_cnt + dst, 1);
    if (pos < CAP) {
        g_csr[dst * CAP + pos] = src;
    } else {
        const int k = atomicAdd(&g_ovf_n, 1);
        if (k < MAX_OVF) g_ovf[k] = e;
    }
}

// ---------------------------------------------------------------------------
// Kernel 3: gather. Half-warp (16 lanes) per node: stream neighbor rows with
// LDG.128 (no atomics), accumulate in registers, write mean row once.
// Edge ids read in int4 batches (same addr across half-warp -> L2 broadcast).
// ---------------------------------------------------------------------------
__global__ __launch_bounds__(256) void gather_kernel(const float* __restrict__ x) {
    const int warp = blockIdx.x * 8 + (threadIdx.x >> 5);
    const int lane = threadIdx.x & 31;
    const int sub  = lane >> 4;
    const int j    = lane & 15;           // float4 slot in the 64-dim row
    const int node = warp * 2 + sub;      // grid covers exactly N_NODES

    const int cnt  = g_cnt[node];
    const int deg  = cnt < CAP ? cnt : CAP;
    const float r  = 1.0f / (float)(cnt > 1 ? cnt : 1);
    const int4* row = reinterpret_cast<const int4*>(g_csr + node * CAP);
    const float4* x4 = reinterpret_cast<const float4*>(x);

    float4 acc = make_float4(0.f, 0.f, 0.f, 0.f);
    for (int e0 = 0; e0 < deg; e0 += 4) {
        const int4 s = __ldg(row + (e0 >> 2));   // broadcast within half-warp
        const int rem = deg - e0;
        float4 v0 = __ldg(x4 + (size_t)s.x * 16 + j);
        float4 v1, v2, v3;
        if (rem > 1) v1 = __ldg(x4 + (size_t)s.y * 16 + j);
        if (rem > 2) v2 = __ldg(x4 + (size_t)s.z * 16 + j);
        if (rem > 3) v3 = __ldg(x4 + (size_t)s.w * 16 + j);
        acc.x += v0.x; acc.y += v0.y; acc.z += v0.z; acc.w += v0.w;
        if (rem > 1) { acc.x += v1.x; acc.y += v1.y; acc.z += v1.z; acc.w += v1.w; }
        if (rem > 2) { acc.x += v2.x; acc.y += v2.y; acc.z += v2.z; acc.w += v2.w; }
        if (rem > 3) { acc.x += v3.x; acc.y += v3.y; acc.z += v3.z; acc.w += v3.w; }
    }
    acc.x *= r; acc.y *= r; acc.z *= r; acc.w *= r;
    reinterpret_cast<float4*>(g_mean)[(size_t)node * 16 + j] = acc;
}

// ---------------------------------------------------------------------------
// Kernel 4: overflow fixup (normally 0 edges). RED x[src]/cnt[dst] into mean.
// ---------------------------------------------------------------------------
__global__ __launch_bounds__(256) void ovf_kernel(const float* __restrict__ x,
                                                  const int* __restrict__ ei) {
    const int n = g_ovf_n < MAX_OVF ? g_ovf_n : MAX_OVF;
    for (int i = threadIdx.x; i < n; i += 256) {
        const int e = g_ovf[i];
        const int src = ei[e], dst = ei[N_EDGES + e];
        const float r = 1.0f / (float)g_cnt[dst];
        #pragma unroll
        for (int q = 0; q < 16; q++) {
            float4 v = __ldg(reinterpret_cast<const float4*>(x) + (size_t)src * 16 + q);
            float* p = g_mean + (size_t)dst * D + q * 4;
            asm volatile("red.global.add.v4.f32 [%0], {%1,%2,%3,%4};"
                         :: "l"(p), "f"(v.x * r), "f"(v.y * r), "f"(v.z * r), "f"(v.w * r)
                         : "memory");
        }
    }
}

// ---------------------------------------------------------------------------
// Kernel 5: out = relu(mean @ Wl^T + b + x @ Wr^T)
// Block: 128 nodes x 64 outputs. 256 threads, each 8 nodes x 4 outputs.
// Packed f32x2 FMA accumulation (2 nodes per 64-bit register).
// ---------------------------------------------------------------------------
#define WPAD 68
#define APAD 132

__global__ __launch_bounds__(256) void out_kernel(
    const float* __restrict__ x,
    const float* __restrict__ Wl,
    const float* __restrict__ bl,
    const float* __restrict__ Wr,
    float* __restrict__ out)
{
    extern __shared__ float sm[];
    float* sWl = sm;                        // [64][WPAD] k-major
    float* sWr = sWl + D * WPAD;            // [64][WPAD]
    float* sA  = sWr + D * WPAD;            // [64][APAD] mean, k-major
    float* sX  = sA  + D * APAD;            // [64][APAD] x, k-major
    float* sB  = sX  + D * APAD;            // [64]

    const int tid = threadIdx.x;
    const int tx  = tid & 15;
    const int ty  = tid >> 4;
    const int node0 = blockIdx.x * 128;

    for (int t = tid; t < 1024; t += 256) {
        const int o = t >> 4, k = (t & 15) * 4;
        float4 w = __ldg(reinterpret_cast<const float4*>(Wl) + t);
        sWl[(k+0)*WPAD+o]=w.x; sWl[(k+1)*WPAD+o]=w.y;
        sWl[(k+2)*WPAD+o]=w.z; sWl[(k+3)*WPAD+o]=w.w;
        float4 u = __ldg(reinterpret_cast<const float4*>(Wr) + t);
        sWr[(k+0)*WPAD+o]=u.x; sWr[(k+1)*WPAD+o]=u.y;
        sWr[(k+2)*WPAD+o]=u.z; sWr[(k+3)*WPAD+o]=u.w;
    }
    if (tid < D) sB[tid] = __ldg(bl + tid);
    __syncthreads();

    for (int t = tid; t < 2048; t += 256) {
        const int node = t >> 4, kq = t & 15, k = kq * 4;
        const int gn = node0 + node;
        float4 a  = make_float4(0.f,0.f,0.f,0.f);
        float4 xv = a;
        if (gn < N_NODES) {
            a  = __ldg(reinterpret_cast<const float4*>(g_mean) + (size_t)gn*16 + kq);
            xv = __ldg(reinterpret_cast<const float4*>(x)      + (size_t)gn*16 + kq);
        }
        sA[(k+0)*APAD+node]=a.x; sA[(k+1)*APAD+node]=a.y;
        sA[(k+2)*APAD+node]=a.z; sA[(k+3)*APAD+node]=a.w;
        sX[(k+0)*APAD+node]=xv.x; sX[(k+1)*APAD+node]=xv.y;
        sX[(k+2)*APAD+node]=xv.z; sX[(k+3)*APAD+node]=xv.w;
    }
    __syncthreads();

    const int nb = ty * 8;
    const int ob = tx * 4;

    unsigned long long acc[4][4];
    #pragma unroll
    for (int o = 0; o < 4; o++) {
        const float b = sB[ob + o];
        unsigned long long bp;
        asm("mov.b64 %0, {%1, %2};" : "=l"(bp) : "f"(b), "f"(b));
        #pragma unroll
        for (int m = 0; m < 4; m++) acc[m][o] = bp;
    }

    #pragma unroll 8
    for (int k = 0; k < D; k++) {
        const float4 wl4 = *reinterpret_cast<const float4*>(sWl + k*WPAD + ob);
        const float4 wr4 = *reinterpret_cast<const float4*>(sWr + k*WPAD + ob);
        const ulonglong2 aA = *reinterpret_cast<const ulonglong2*>(sA + k*APAD + nb);
        const ulonglong2 aB = *reinterpret_cast<const ulonglong2*>(sA + k*APAD + nb + 4);
        const ulonglong2 xA = *reinterpret_cast<const ulonglong2*>(sX + k*APAD + nb);
        const ulonglong2 xB = *reinterpret_cast<const ulonglong2*>(sX + k*APAD + nb + 4);
        const unsigned long long ap[4] = {aA.x, aA.y, aB.x, aB.y};
        const unsigned long long xp[4] = {xA.x, xA.y, xB.x, xB.y};
        const float wlv[4] = {wl4.x, wl4.y, wl4.z, wl4.w};
        const float wrv[4] = {wr4.x, wr4.y, wr4.z, wr4.w};
        #pragma unroll
        for (int o = 0; o < 4; o++) {
            unsigned long long wl2, wr2;
            asm("mov.b64 %0, {%1, %2};" : "=l"(wl2) : "f"(wlv[o]), "f"(wlv[o]));
            asm("mov.b64 %0, {%1, %2};" : "=l"(wr2) : "f"(wrv[o]), "f"(wrv[o]));
            #pragma unroll
            for (int m = 0; m < 4; m++) {
                asm("fma.rn.f32x2 %0, %1, %2, %0;" : "+l"(acc[m][o]) : "l"(ap[m]), "l"(wl2));
                asm("fma.rn.f32x2 %0, %1, %2, %0;" : "+l"(acc[m][o]) : "l"(xp[m]), "l"(wr2));
            }
        }
    }

    #pragma unroll
    for (int m = 0; m < 4; m++) {
        float lo[4], hi[4];
        #pragma unroll
        for (int o = 0; o < 4; o++)
            asm("mov.b64 {%0, %1}, %2;" : "=f"(lo[o]), "=f"(hi[o]) : "l"(acc[m][o]));
        const int g0 = node0 + nb + m * 2;
        if (g0 < N_NODES) {
            float4 v = make_float4(fmaxf(lo[0],0.f), fmaxf(lo[1],0.f),
                                   fmaxf(lo[2],0.f), fmaxf(lo[3],0.f));
            *reinterpret_cast<float4*>(out + (size_t)g0*D + ob) = v;
        }
        if (g0 + 1 < N_NODES) {
            float4 v = make_float4(fmaxf(hi[0],0.f), fmaxf(hi[1],0.f),
                                   fmaxf(hi[2],0.f), fmaxf(hi[3],0.f));
            *reinterpret_cast<float4*>(out + (size_t)(g0+1)*D + ob) = v;
        }
    }
}

// ---------------------------------------------------------------------------
extern "C" void kernel_launch(void* const* d_in, const int* in_sizes, int n_in,
                              void* d_out, int out_size)
{
    const float* x  = (const float*)d_in[0];
    const int*   ei = (const int*)d_in[1];     // int32 (JAX x64 disabled)
    const float* Wl = (const float*)d_in[2];
    const float* bl = (const float*)d_in[3];
    const float* Wr = (const float*)d_in[4];
    float* out = (float*)d_out;

    const int smem_bytes = (2 * D * WPAD + 2 * D * APAD + D) * sizeof(float);
    cudaFuncSetAttribute(out_kernel, cudaFuncAttributeMaxDynamicSharedMemorySize, smem_bytes);

    zero_kernel<<<256, 256>>>();
    fill_kernel<<<(N_EDGES + 255) / 256, 256>>>(ei);
    gather_kernel<<<N_NODES / 16, 256>>>(x);        // 2 nodes/warp * 8 warps = 16/block
    ovf_kernel<<<1, 256>>>(x, ei);
    out_kernel<<<(N_NODES + 127) / 128, 256, smem_bytes>>>(x, Wl, bl, Wr, out);
}